// round 2
// baseline (speedup 1.0000x reference)
#include <cuda_runtime.h>
#include <cstdint>

// x: [65536, 512] fp32 in [0,1)
// out: [65536, 512*3] fp32, bits of q = round_half_even(x*8 - 0.5), MSB-first per element.
//
// Memory-bound: 128 MiB read + 384 MiB write -> HBM roofline ~75-85 us.
// Strategy: float4 load -> 3x uint4 store (bit value encoded as 0x3F800000 mask, no I2F).

__global__ void quant_bits_kernel(const float4* __restrict__ in,
                                  uint4* __restrict__ out,
                                  int n4) {
    int i = blockIdx.x * blockDim.x + threadIdx.x;
    if (i >= n4) return;

    float4 v = in[i];
    float xs[4] = {v.x, v.y, v.z, v.w};
    unsigned b[12];

#pragma unroll
    for (int j = 0; j < 4; j++) {
        // x*8 is exact in fp32 (power-of-2 scale), so fma == (x*8)-0.5 with one rounding,
        // identical to the reference. __float2int_rn = round-half-to-even, matching jnp.round.
        int q = __float2int_rn(fmaf(xs[j], 8.0f, -0.5f));
        // bit -> fp32 1.0f/0.0f without I2F: -(bit) & 0x3F800000
        b[j * 3 + 0] = (unsigned)(-((q >> 2) & 1)) & 0x3F800000u;
        b[j * 3 + 1] = (unsigned)(-((q >> 1) & 1)) & 0x3F800000u;
        b[j * 3 + 2] = (unsigned)(-(q & 1)) & 0x3F800000u;
    }

    uint4* o = out + (size_t)i * 3;
    o[0] = make_uint4(b[0], b[1], b[2], b[3]);
    o[1] = make_uint4(b[4], b[5], b[6], b[7]);
    o[2] = make_uint4(b[8], b[9], b[10], b[11]);
}

extern "C" void kernel_launch(void* const* d_in, const int* in_sizes, int n_in,
                              void* d_out, int out_size) {
    const float4* in = (const float4*)d_in[0];
    uint4* out = (uint4*)d_out;
    int n = in_sizes[0];          // 65536*512 = 2^25 elements
    int n4 = n >> 2;              // 2^23 float4s
    int threads = 256;
    int blocks = (n4 + threads - 1) / threads;
    quant_bits_kernel<<<blocks, threads>>>(in, out, n4);
}

// round 3
// speedup vs baseline: 1.1705x; 1.1705x over previous
#include <cuda_runtime.h>
#include <cstdint>

// x: [65536, 512] fp32 in [0,1)
// out: [65536, 1536] fp32: 3 bits (MSB-first) of q = round_half_even(x*8 - 0.5) per element.
//
// R2 lesson: direct out[3i+c] stores gave 48B lane stride -> 3x L1 store wavefronts +
// partial-sector DRAM writes (L1 78.6%, DRAM 58.5%). Stage stores through smem so the
// global drain is fully coalesced full-sector uint4 stores.

constexpr int THREADS = 256;
constexpr int OUT4_PER_BLOCK = THREADS * 3;  // 768 uint4 = 12 KB

__global__ void __launch_bounds__(THREADS) quant_bits_kernel(
    const float4* __restrict__ in, uint4* __restrict__ out, int n4) {
    __shared__ uint4 s[OUT4_PER_BLOCK];

    int tid = threadIdx.x;
    int i = blockIdx.x * THREADS + tid;

    if (i < n4) {
        float4 v = in[i];
        float xs[4] = {v.x, v.y, v.z, v.w};
        unsigned b[12];
#pragma unroll
        for (int j = 0; j < 4; j++) {
            // x*8 exact in fp32 (pow2 scale) -> fma == (x*8)-0.5 with one rounding,
            // identical to reference. __float2int_rn = round-half-to-even (jnp.round).
            int q = __float2int_rn(fmaf(xs[j], 8.0f, -0.5f));
            // bit -> fp32 1.0f/0.0f without I2F: -(bit) & 0x3F800000
            b[j * 3 + 0] = (unsigned)(-((q >> 2) & 1)) & 0x3F800000u;
            b[j * 3 + 1] = (unsigned)(-((q >> 1) & 1)) & 0x3F800000u;
            b[j * 3 + 2] = (unsigned)(-(q & 1)) & 0x3F800000u;
        }
        // STS pattern s[3t+c]: within each 8-lane .128 phase, banks 12t mod 32 cover
        // all 32 banks -> conflict-free.
        s[3 * tid + 0] = make_uint4(b[0], b[1], b[2], b[3]);
        s[3 * tid + 1] = make_uint4(b[4], b[5], b[6], b[7]);
        s[3 * tid + 2] = make_uint4(b[8], b[9], b[10], b[11]);
    }
    __syncthreads();

    // Coalesced drain: block's output span is contiguous [blockIdx*768, +768) uint4s.
    size_t base = (size_t)blockIdx.x * OUT4_PER_BLOCK;
    size_t out_limit = (size_t)n4 * 3;
#pragma unroll
    for (int k = 0; k < 3; k++) {
        size_t idx = base + k * THREADS + tid;
        if (idx < out_limit) out[idx] = s[k * THREADS + tid];
    }
}

extern "C" void kernel_launch(void* const* d_in, const int* in_sizes, int n_in,
                              void* d_out, int out_size) {
    const float4* in = (const float4*)d_in[0];
    uint4* out = (uint4*)d_out;
    int n = in_sizes[0];   // 2^25 elements
    int n4 = n >> 2;       // 2^23 float4s
    int blocks = (n4 + THREADS - 1) / THREADS;
    quant_bits_kernel<<<blocks, THREADS>>>(in, out, n4);
}